// round 1
// baseline (speedup 1.0000x reference)
#include <cuda_runtime.h>

#define N_NODES 8192
#define F_DIM   128
#define TI      64      // rows per block in attention kernel
#define JT      32      // j-chunk
#define ALPHA_S 0.2f

// ---- scratch (no allocations allowed) ----
__device__ float g_h[N_NODES * F_DIM];     // h = x * W
__device__ float g_f1[N_NODES];
__device__ float g_f2[N_NODES];
__device__ float g_e1p[N_NODES];           // exp(f1)
__device__ float g_e1m[N_NODES];           // exp(alpha*f1)
__device__ float g_e2p[N_NODES];           // exp(f2)
__device__ float g_e2m[N_NODES];           // exp(alpha*f2)
__device__ float g_r[N_NODES];             // adj @ W2

// ---------------------------------------------------------------------------
// Kernel 1: h = x*W ; f1 = h@a[:F] ; f2 = h@a[F:] ; precompute 4 exp arrays.
// One block (128 threads) per row.
// ---------------------------------------------------------------------------
__global__ void prep_kernel(const float* __restrict__ x,
                            const float* __restrict__ W,
                            const float* __restrict__ a) {
    int i = blockIdx.x;
    int f = threadIdx.x;
    float hv = x[i * F_DIM + f] * W[i * F_DIM + f];
    g_h[i * F_DIM + f] = hv;

    float p1 = hv * a[f];
    float p2 = hv * a[F_DIM + f];
    #pragma unroll
    for (int off = 16; off; off >>= 1) {
        p1 += __shfl_down_sync(0xffffffffu, p1, off);
        p2 += __shfl_down_sync(0xffffffffu, p2, off);
    }
    __shared__ float s1[4], s2[4];
    int lane = f & 31, wid = f >> 5;
    if (lane == 0) { s1[wid] = p1; s2[wid] = p2; }
    __syncthreads();
    if (f == 0) {
        float f1v = s1[0] + s1[1] + s1[2] + s1[3];
        float f2v = s2[0] + s2[1] + s2[2] + s2[3];
        g_f1[i] = f1v;
        g_f2[i] = f2v;
        g_e1p[i] = expf(f1v);
        g_e1m[i] = expf(ALPHA_S * f1v);
        g_e2p[i] = expf(f2v);
        g_e2m[i] = expf(ALPHA_S * f2v);
    }
}

// ---------------------------------------------------------------------------
// Kernel 2: fused masked-softmax attention GEMM + r = adj @ W2.
//   W_ij = adj_ij * ((f1_i+f2_j >= 0) ? e1p_i*e2p_j : e1m_i*e2m_j)
//   h_prime[i,:] = (sum_j W_ij * h[j,:]) / (sum_j W_ij)
// Block: 256 threads = (32 f-lanes) x (8 warps). Each warp owns 8 rows.
// Each thread: acc[8 rows][4 cols], i.e. cols f = tx*4..tx*4+3.
// adj is read exactly once (streamed), also feeding r.
// ---------------------------------------------------------------------------
__global__ __launch_bounds__(256) void attn_kernel(const int* __restrict__ adj,
                                                   const float* __restrict__ W2,
                                                   float* __restrict__ hp) {
    int i0 = blockIdx.x * TI;
    int tx = threadIdx.x & 31;   // f-group index / j lane
    int w  = threadIdx.x >> 5;   // warp id 0..7 -> rows i0 + w*8 + k

    __shared__ float h_s[JT][F_DIM];
    __shared__ float W_s[TI][JT];

    float acc[8][4];
    float zp[8], rp[8];
    #pragma unroll
    for (int k = 0; k < 8; k++) {
        zp[k] = 0.f; rp[k] = 0.f;
        acc[k][0] = acc[k][1] = acc[k][2] = acc[k][3] = 0.f;
    }

    // per-row constants (fixed for the whole kernel)
    float f1r[8], e1pr[8], e1mr[8];
    #pragma unroll
    for (int k = 0; k < 8; k++) {
        int row = i0 + w * 8 + k;
        f1r[k]  = g_f1[row];
        e1pr[k] = g_e1p[row];
        e1mr[k] = g_e1m[row];
    }

    // --- software pipeline: preload chunk 0 (adj + h + j-constants) ---
    int   av[8];
    float f2v, e2pv, e2mv, w2v;
    float4 hreg[4];
    {
        int j = tx;
        f2v  = g_f2[j];  e2pv = g_e2p[j];  e2mv = g_e2m[j];  w2v = W2[j];
        #pragma unroll
        for (int k = 0; k < 8; k++)
            av[k] = __ldcs(&adj[(i0 + w * 8 + k) * N_NODES + j]);
        #pragma unroll
        for (int t = 0; t < 4; t++) {
            int p = threadIdx.x + t * 256;
            int row = p >> 5, c4 = p & 31;
            hreg[t] = *(const float4*)&g_h[row * F_DIM + c4 * 4];
        }
    }

    for (int j0 = 0; j0 < N_NODES; j0 += JT) {
        // stage h tile from prefetched regs
        #pragma unroll
        for (int t = 0; t < 4; t++) {
            int p = threadIdx.x + t * 256;
            int row = p >> 5, c4 = p & 31;
            *(float4*)&h_s[row][c4 * 4] = hreg[t];
        }
        // build coefficient tile + Z and r accumulation
        #pragma unroll
        for (int k = 0; k < 8; k++) {
            float s  = f1r[k] + f2v;
            float wv = (s >= 0.f) ? e1pr[k] * e2pv : e1mr[k] * e2mv;
            wv = av[k] ? wv : 0.f;
            W_s[w * 8 + k][tx] = wv;
            zp[k] += wv;
            if (av[k]) rp[k] += w2v;
        }
        // prefetch next chunk (overlaps with GEMM below)
        int j1 = j0 + JT;
        if (j1 < N_NODES) {
            int j = j1 + tx;
            f2v  = g_f2[j];  e2pv = g_e2p[j];  e2mv = g_e2m[j];  w2v = W2[j];
            #pragma unroll
            for (int k = 0; k < 8; k++)
                av[k] = __ldcs(&adj[(i0 + w * 8 + k) * N_NODES + j]);
            #pragma unroll
            for (int t = 0; t < 4; t++) {
                int p = threadIdx.x + t * 256;
                int row = p >> 5, c4 = p & 31;
                hreg[t] = *(const float4*)&g_h[(j1 + row) * F_DIM + c4 * 4];
            }
        }
        __syncthreads();
        // register-blocked GEMM on the tile
        #pragma unroll 8
        for (int jj = 0; jj < JT; jj++) {
            float4 hv = *(const float4*)&h_s[jj][tx * 4];
            #pragma unroll
            for (int k = 0; k < 8; k++) {
                float wv = W_s[w * 8 + k][jj];
                acc[k][0] += wv * hv.x;
                acc[k][1] += wv * hv.y;
                acc[k][2] += wv * hv.z;
                acc[k][3] += wv * hv.w;
            }
        }
        __syncthreads();
    }

    // reduce Z and r across the 32 lanes (each lane covered j = lane mod 32)
    #pragma unroll
    for (int k = 0; k < 8; k++) {
        #pragma unroll
        for (int off = 16; off; off >>= 1) {
            zp[k] += __shfl_xor_sync(0xffffffffu, zp[k], off);
            rp[k] += __shfl_xor_sync(0xffffffffu, rp[k], off);
        }
    }
    if (tx == 0) {
        #pragma unroll
        for (int k = 0; k < 8; k++)
            g_r[i0 + w * 8 + k] = rp[k];
    }
    // write h_prime = acc / Z
    #pragma unroll
    for (int k = 0; k < 8; k++) {
        float inv = 1.0f / zp[k];
        float4 o;
        o.x = acc[k][0] * inv;
        o.y = acc[k][1] * inv;
        o.z = acc[k][2] * inv;
        o.w = acc[k][3] * inv;
        *(float4*)&hp[(i0 + w * 8 + k) * F_DIM + tx * 4] = o;
    }
}

// ---------------------------------------------------------------------------
// Kernel 3: out[f] = elu( sum_i r[i] * x[i,f] ).  One block per f.
// ---------------------------------------------------------------------------
__global__ void out_kernel(const float* __restrict__ x,
                           float* __restrict__ out) {
    int f = blockIdx.x;
    float p = 0.f;
    for (int i = threadIdx.x; i < N_NODES; i += 256)
        p += g_r[i] * x[i * F_DIM + f];
    #pragma unroll
    for (int off = 16; off; off >>= 1)
        p += __shfl_xor_sync(0xffffffffu, p, off);
    __shared__ float s[8];
    int lane = threadIdx.x & 31, wid = threadIdx.x >> 5;
    if (lane == 0) s[wid] = p;
    __syncthreads();
    if (threadIdx.x == 0) {
        float v = 0.f;
        #pragma unroll
        for (int k = 0; k < 8; k++) v += s[k];
        out[f] = (v > 0.f) ? v : (expf(v) - 1.0f);
    }
}

// ---------------------------------------------------------------------------
extern "C" void kernel_launch(void* const* d_in, const int* in_sizes, int n_in,
                              void* d_out, int out_size) {
    const float* x   = (const float*)d_in[0];
    const int*   adj = (const int*)  d_in[1];
    const float* W   = (const float*)d_in[2];
    const float* a   = (const float*)d_in[3];
    const float* W2  = (const float*)d_in[4];
    float* out = (float*)d_out;                 // [0:128) = elu output, [128:) = h_prime

    prep_kernel<<<N_NODES, F_DIM>>>(x, W, a);
    attn_kernel<<<N_NODES / TI, 256>>>(adj, W2, out + F_DIM);
    out_kernel<<<F_DIM, 256>>>(x, out);
}